// round 8
// baseline (speedup 1.0000x reference)
#include <cuda_runtime.h>
#include <math.h>

#define NTOK 8192
#define DDIM 1024
#define NEXP 16
#define GRP  8               // tokens per group
#define NGRPS 2              // groups per block
#define TPB  (GRP * NGRPS)   // 16 tokens per block
#define NBLK (NTOK / TPB)    // 512 blocks -> ~3 blocks/SM resident
#define FULL 0xffffffffu
#define HBUF (GRP * DDIM)    // floats per h buffer

// ---- scratch (device globals: no allocation allowed) ----
__device__ float g_S[DDIM];          // column sums of h^2 ; zero at load, re-zeroed each iter
__device__ float g_G[NEXP * NEXP];   // Gram matrix
__device__ int   g_cnt;              // gram completion ticket (zero-init, reset each iter)

__device__ __forceinline__ void cpasync16(float* dst, const float* src) {
    unsigned d = (unsigned)__cvta_generic_to_shared(dst);
    asm volatile("cp.async.cg.shared.global [%0], [%1], 16;" :: "r"(d), "l"(src));
}
__device__ __forceinline__ void cp_commit() { asm volatile("cp.async.commit_group;"); }
__device__ __forceinline__ void cp_wait0()  { asm volatile("cp.async.wait_group 0;"); }

// ============================================================================
// K1: fused router + combine. Double-buffered cp.async h staging (64 KB dyn),
//   512 blocks x 256 thr, ~3 blocks/SM. Warp = expert-pair for logits (gate
//   streamed from L2); serial-scan router; dim-sliced combine. 2 barriers/group.
// ============================================================================
extern "C" __global__ void __launch_bounds__(256, 3)
moe_main(const float* __restrict__ x,
         const float* __restrict__ gate_w,
         const float* __restrict__ gate_b,
         const float* __restrict__ sh_e,
         const float* __restrict__ rt_e,
         float* __restrict__ out)
{
    extern __shared__ float h_s[];         // 2 * 32 KB
    __shared__ float logit_s[GRP * 17];    // padded stride 17 (bias folded in)

    const int tid  = threadIdx.x;
    const int warp = tid >> 5;
    const int lane = tid & 31;
    const int tok0 = blockIdx.x * TPB;

    // ---- prefetch group 0 ----
    #pragma unroll
    for (int i = 0; i < 8; i++)
        cpasync16(&h_s[4 * (i * 256 + tid)],
                  x + (size_t)tok0 * DDIM + 4 * (i * 256 + tid));
    cp_commit();

    // gate rows for this warp (streamed per group from L2)
    const float4* gwp = (const float4*)(gate_w + 2 * warp * DDIM) + lane;
    const float biasA = __ldg(&gate_b[2 * warp]);
    const float biasB = __ldg(&gate_b[2 * warp + 1]);

    // ---- combine dim-slice + shared-expert sum in regs ----
    const int d0 = 128 * warp + 4 * lane;
    float4 sh4;
    {
        float4 a = *(const float4*)(sh_e + d0);
        float4 b = *(const float4*)(sh_e + DDIM + d0);
        sh4.x = a.x + b.x; sh4.y = a.y + b.y; sh4.z = a.z + b.z; sh4.w = a.w + b.w;
    }
    float s4x = 0.f, s4y = 0.f, s4z = 0.f, s4w = 0.f;   // h^2 partials

    #pragma unroll
    for (int grp = 0; grp < NGRPS; grp++) {
        const int tbase = tok0 + grp * GRP;
        const float* hbuf = h_s + (grp & 1) * HBUF;

        cp_wait0();          // group `grp` landed
        __syncthreads();     // visible to all; all warps done with group grp-1

        // ---- prefetch grp+1 into the other buffer (freed by the barrier) ----
        if (grp + 1 < NGRPS) {
            const float* src = x + (size_t)(tbase + GRP) * DDIM;
            float* dst = h_s + ((grp + 1) & 1) * HBUF;
            #pragma unroll
            for (int i = 0; i < 8; i++)
                cpasync16(&dst[4 * (i * 256 + tid)], src + 4 * (i * 256 + tid));
        }
        cp_commit();

        // ---- logits: this warp's 2 experts x 8 tokens ----
        float acc[16];
        #pragma unroll
        for (int j = 0; j < 16; j++) acc[j] = 0.f;
        #pragma unroll
        for (int i = 0; i < 8; i++) {
            const float4 g0 = __ldg(gwp + 32 * i);
            const float4 g1 = __ldg(gwp + 256 + 32 * i);
            #pragma unroll
            for (int t = 0; t < 8; t++) {
                float4 h4 = *(const float4*)&hbuf[t * DDIM + 4 * lane + 128 * i];
                acc[2 * t]     += g0.x * h4.x + g0.y * h4.y + g0.z * h4.z + g0.w * h4.w;
                acc[2 * t + 1] += g1.x * h4.x + g1.y * h4.y + g1.z * h4.z + g1.w * h4.w;
            }
        }

        // ---- reduce-scatter 16 accs across 32 lanes ----
        // final: lane l holds full sum of acc[(l>>1)&15]
        float v8[8];
        #pragma unroll
        for (int j = 0; j < 8; j++) {
            float send = (lane & 16) ? acc[j] : acc[j + 8];
            float recv = __shfl_xor_sync(FULL, send, 16);
            v8[j] = ((lane & 16) ? acc[j + 8] : acc[j]) + recv;
        }
        float v4[4];
        #pragma unroll
        for (int j = 0; j < 4; j++) {
            float send = (lane & 8) ? v8[j] : v8[j + 4];
            float recv = __shfl_xor_sync(FULL, send, 8);
            v4[j] = ((lane & 8) ? v8[j + 4] : v8[j]) + recv;
        }
        float v2[2];
        #pragma unroll
        for (int j = 0; j < 2; j++) {
            float s2 = (lane & 4) ? v4[j] : v4[j + 2];
            float r2 = __shfl_xor_sync(FULL, s2, 4);
            v2[j] = ((lane & 4) ? v4[j + 2] : v4[j]) + r2;
        }
        float s1 = (lane & 2) ? v2[0] : v2[1];
        float r1 = __shfl_xor_sync(FULL, s1, 2);
        float z  = ((lane & 2) ? v2[1] : v2[0]) + r1;
        z += __shfl_xor_sync(FULL, z, 1);

        if (!(lane & 1)) {
            const int j = (lane >> 1) & 15;              // j = 2*t + esub
            const int esub = j & 1;
            logit_s[(j >> 1) * 17 + 2 * warp + esub] = z + (esub ? biasB : biasA);
        }
        __syncthreads();

        // ---- router: serial top-2 scan; lane routes token (lane & 7) ----
        const int t_r = lane & 7;
        float v1 = -1e30f, vv2 = -1e30f; int j1 = 0, j2 = 0;
        #pragma unroll
        for (int e = 0; e < NEXP; e++) {
            float lg = logit_s[t_r * 17 + e];
            if (lg > v1)       { vv2 = v1; j2 = j1; v1 = lg; j1 = e; }
            else if (lg > vv2) { vv2 = lg; j2 = e; }
        }
        const float w0s = 1.f / (1.f + __expf(vv2 - v1));   // softmax denom cancels
        const int i0s = j1, i1s = j2;

        // ---- combine (dim-sliced): warp covers dims [128w, 128w+128) ----
        #pragma unroll
        for (int t = 0; t < 8; t++) {
            const float w0 = __shfl_sync(FULL, w0s, t);
            const int   i0 = __shfl_sync(FULL, i0s, t);
            const int   i1 = __shfl_sync(FULL, i1s, t);
            const float w1 = 1.f - w0;
            float4 h4 = *(const float4*)&hbuf[t * DDIM + d0];
            float4 r0 = __ldg((const float4*)(rt_e + i0 * DDIM + d0));
            float4 r1 = __ldg((const float4*)(rt_e + i1 * DDIM + d0));
            float4 o;
            o.x = h4.x * (sh4.x + w0 * r0.x + w1 * r1.x);
            o.y = h4.y * (sh4.y + w0 * r0.y + w1 * r1.y);
            o.z = h4.z * (sh4.z + w0 * r0.z + w1 * r1.z);
            o.w = h4.w * (sh4.w + w0 * r0.w + w1 * r1.w);
            *(float4*)(out + (size_t)(tbase + t) * DDIM + d0) = o;
            s4x += h4.x * h4.x; s4y += h4.y * h4.y;
            s4z += h4.z * h4.z; s4w += h4.w * h4.w;
        }
        // no end-of-group barrier: next group's barrier protects buffers
    }

    atomicAdd(&g_S[d0 + 0], s4x);
    atomicAdd(&g_S[d0 + 1], s4y);
    atomicAdd(&g_S[d0 + 2], s4z);
    atomicAdd(&g_S[d0 + 3], s4w);
}

// ============================================================================
// K2: Gram rows G[e,f] = sum_d r_e[d]*r_f[d]*S[d]; LAST block computes the
//   diversity loss, re-zeros g_S and resets the ticket (graph-replay safe).
// ============================================================================
extern "C" __global__ void __launch_bounds__(256, 1)
moe_gram(const float* __restrict__ rt_e, float* __restrict__ out,
         int has_loss, int loss_idx)
{
    __shared__ float red[8 * NEXP];
    __shared__ int ticket;
    const int tid = threadIdx.x;
    const int e = blockIdx.x;

    float acc[NEXP];
    #pragma unroll
    for (int f = 0; f < NEXP; f++) acc[f] = 0.f;

    for (int d = tid; d < DDIM; d += 256) {
        float v = __ldg(&rt_e[e * DDIM + d]) * g_S[d];
        #pragma unroll
        for (int f = 0; f < NEXP; f++) acc[f] += v * __ldg(&rt_e[f * DDIM + d]);
    }

    const int wid = tid >> 5, lane = tid & 31;
    #pragma unroll
    for (int f = 0; f < NEXP; f++) {
        #pragma unroll
        for (int off = 16; off; off >>= 1)
            acc[f] += __shfl_xor_sync(FULL, acc[f], off);
    }
    if (lane == 0) {
        #pragma unroll
        for (int f = 0; f < NEXP; f++) red[wid * NEXP + f] = acc[f];
    }
    __syncthreads();
    if (tid < NEXP) {
        float s = 0.f;
        #pragma unroll
        for (int w = 0; w < 8; w++) s += red[w * NEXP + tid];
        g_G[e * NEXP + tid] = s;
    }

    // ---- arrival ticket: last block finalizes ----
    __threadfence();
    __syncthreads();
    if (tid == 0) ticket = atomicAdd(&g_cnt, 1);
    __syncthreads();
    if (ticket == NEXP - 1) {
        if (tid < 32) {
            const int ee = tid & 15;
            float n = sqrtf(g_G[ee * NEXP + ee]);
            n = fmaxf(n, 1e-8f);
            float s = 0.f;
            #pragma unroll
            for (int f = 0; f < NEXP; f++) {
                float nf = __shfl_sync(FULL, n, f);
                if (f != ee) {
                    float sim = g_G[ee * NEXP + f] / (n * nf);
                    sim = fminf(1.f, fmaxf(-1.f, sim));
                    s += sim;
                }
            }
            if (tid >= 16) s = 0.f;
            #pragma unroll
            for (int off = 16; off; off >>= 1) s += __shfl_xor_sync(FULL, s, off);
            if (tid == 0 && has_loss)
                out[loss_idx] = s / (float)(NEXP * (NEXP - 1)) * 0.1f;
        }
        // restore invariants for next graph replay
        for (int i = tid; i < DDIM; i += 256) g_S[i] = 0.f;
        if (tid == 0) g_cnt = 0;
    }
}

// ============================================================================
extern "C" void kernel_launch(void* const* d_in, const int* in_sizes, int n_in,
                              void* d_out, int out_size)
{
    const float* x  = (const float*)d_in[0];
    const float* gw = (const float*)d_in[1];
    const float* gb = (const float*)d_in[2];
    const float* se = (const float*)d_in[3];
    const float* re = (const float*)d_in[4];
    float* out = (float*)d_out;

    const int SMEM1 = 2 * HBUF * (int)sizeof(float);   // 64 KB dynamic
    cudaFuncSetAttribute((const void*)moe_main,
                         cudaFuncAttributeMaxDynamicSharedMemorySize, SMEM1);

    moe_main<<<NBLK, 256, SMEM1>>>(x, gw, gb, se, re, out);

    int has_loss = (out_size > NTOK * DDIM) ? 1 : 0;
    moe_gram<<<NEXP, 256>>>(re, out, has_loss, out_size - 1);
}

// round 9
// speedup vs baseline: 1.3471x; 1.3471x over previous
#include <cuda_runtime.h>
#include <math.h>

#define NTOK 8192
#define DDIM 1024
#define NEXP 16
#define GRP  8               // tokens per group
#define NGRPS 4              // groups per block
#define TPB  (GRP * NGRPS)   // 32 tokens per block
#define NBLK (NTOK / TPB)    // 256 blocks
#define FULL 0xffffffffu
#define HBUF (GRP * DDIM)    // floats per h buffer

// ---- scratch (device globals: no allocation allowed) ----
__device__ float g_S[DDIM];          // column sums of h^2 ; zero at load, re-zeroed by moe_loss
__device__ float g_G[NEXP * NEXP];   // Gram accumulator; zero at load, re-zeroed by moe_loss

__device__ __forceinline__ void cpasync16(float* dst, const float* src) {
    unsigned d = (unsigned)__cvta_generic_to_shared(dst);
    asm volatile("cp.async.cg.shared.global [%0], [%1], 16;" :: "r"(d), "l"(src));
}
__device__ __forceinline__ void cp_commit() { asm volatile("cp.async.commit_group;"); }
__device__ __forceinline__ void cp_wait1()  { asm volatile("cp.async.wait_group 1;"); }

// ============================================================================
// K1 (exact R5 config, 34.1us proven): fused router + combine.
//   Triple-buffered cp.async h staging (96 KB dyn), 2 blocks/SM, gate rows
//   register-resident, serial-scan router, dim-sliced combine, 2 barriers/group.
// ============================================================================
extern "C" __global__ void __launch_bounds__(256, 2)
moe_main(const float* __restrict__ x,
         const float* __restrict__ gate_w,
         const float* __restrict__ gate_b,
         const float* __restrict__ sh_e,
         const float* __restrict__ rt_e,
         float* __restrict__ out)
{
    extern __shared__ float h_s[];         // 3 * 32 KB
    __shared__ float logit_s[GRP * 17];    // padded stride 17 (bias folded in)

    const int tid  = threadIdx.x;
    const int warp = tid >> 5;
    const int lane = tid & 31;
    const int tok0 = blockIdx.x * TPB;

    // ---- prefetch groups 0 and 1 ----
    #pragma unroll
    for (int i = 0; i < 8; i++)
        cpasync16(&h_s[0 * HBUF + 4 * (i * 256 + tid)],
                  x + (size_t)tok0 * DDIM + 4 * (i * 256 + tid));
    cp_commit();
    #pragma unroll
    for (int i = 0; i < 8; i++)
        cpasync16(&h_s[1 * HBUF + 4 * (i * 256 + tid)],
                  x + (size_t)(tok0 + GRP) * DDIM + 4 * (i * 256 + tid));
    cp_commit();

    // ---- gate rows 2*warp, 2*warp+1 in registers (float4, d = 4*lane + 128*i) ----
    float4 ga4[8], gb4[8];
    {
        const float4* gwp = (const float4*)(gate_w + 2 * warp * DDIM);
        #pragma unroll
        for (int i = 0; i < 8; i++) {
            ga4[i] = gwp[32 * i + lane];
            gb4[i] = gwp[256 + 32 * i + lane];
        }
    }
    const float biasA = __ldg(&gate_b[2 * warp]);
    const float biasB = __ldg(&gate_b[2 * warp + 1]);

    // ---- combine dim-slice + shared-expert sum in regs ----
    const int d0 = 128 * warp + 4 * lane;
    float4 sh4;
    {
        float4 a = *(const float4*)(sh_e + d0);
        float4 b = *(const float4*)(sh_e + DDIM + d0);
        sh4.x = a.x + b.x; sh4.y = a.y + b.y; sh4.z = a.z + b.z; sh4.w = a.w + b.w;
    }
    float s4x = 0.f, s4y = 0.f, s4z = 0.f, s4w = 0.f;   // h^2 partials

    #pragma unroll
    for (int grp = 0; grp < NGRPS; grp++) {
        const int tbase = tok0 + grp * GRP;
        const float* hbuf = h_s + (grp % 3) * HBUF;

        cp_wait1();          // group `grp` landed
        __syncthreads();     // visible to all; all warps past group grp-1 combine

        // ---- early prefetch grp+2 into buffer (grp+2)%3 ----
        if (grp + 2 < NGRPS) {
            const float* src = x + (size_t)(tok0 + (grp + 2) * GRP) * DDIM;
            float* dst = h_s + ((grp + 2) % 3) * HBUF;
            #pragma unroll
            for (int i = 0; i < 8; i++)
                cpasync16(&dst[4 * (i * 256 + tid)], src + 4 * (i * 256 + tid));
        }
        cp_commit();         // commit every group to keep wait-counts aligned

        // ---- logits: this warp's 2 experts x 8 tokens ----
        float acc[16];
        #pragma unroll
        for (int t = 0; t < 8; t++) {
            float aA = 0.f, aB = 0.f;
            #pragma unroll
            for (int i = 0; i < 8; i++) {
                float4 h4 = *(const float4*)&hbuf[t * DDIM + 4 * lane + 128 * i];
                float4 g0 = ga4[i], g1 = gb4[i];
                aA += g0.x * h4.x + g0.y * h4.y + g0.z * h4.z + g0.w * h4.w;
                aB += g1.x * h4.x + g1.y * h4.y + g1.z * h4.z + g1.w * h4.w;
            }
            acc[2 * t]     = aA;
            acc[2 * t + 1] = aB;
        }

        // ---- reduce-scatter 16 accs across 32 lanes ----
        // final: lane l holds full sum of acc[(l>>1)&15]
        float v8[8];
        #pragma unroll
        for (int j = 0; j < 8; j++) {
            float send = (lane & 16) ? acc[j] : acc[j + 8];
            float recv = __shfl_xor_sync(FULL, send, 16);
            v8[j] = ((lane & 16) ? acc[j + 8] : acc[j]) + recv;
        }
        float v4[4];
        #pragma unroll
        for (int j = 0; j < 4; j++) {
            float send = (lane & 8) ? v8[j] : v8[j + 4];
            float recv = __shfl_xor_sync(FULL, send, 8);
            v4[j] = ((lane & 8) ? v8[j + 4] : v8[j]) + recv;
        }
        float v2[2];
        #pragma unroll
        for (int j = 0; j < 2; j++) {
            float s2 = (lane & 4) ? v4[j] : v4[j + 2];
            float r2 = __shfl_xor_sync(FULL, s2, 4);
            v2[j] = ((lane & 4) ? v4[j + 2] : v4[j]) + r2;
        }
        float s1 = (lane & 2) ? v2[0] : v2[1];
        float r1 = __shfl_xor_sync(FULL, s1, 2);
        float z  = ((lane & 2) ? v2[1] : v2[0]) + r1;
        z += __shfl_xor_sync(FULL, z, 1);

        if (!(lane & 1)) {
            const int j = (lane >> 1) & 15;              // j = 2*t + esub
            const int esub = j & 1;
            logit_s[(j >> 1) * 17 + 2 * warp + esub] = z + (esub ? biasB : biasA);
        }
        __syncthreads();

        // ---- router: serial top-2 scan; lane routes token (lane & 7) ----
        const int t_r = lane & 7;
        float v1 = -1e30f, vv2 = -1e30f; int j1 = 0, j2 = 0;
        #pragma unroll
        for (int e = 0; e < NEXP; e++) {
            float lg = logit_s[t_r * 17 + e];
            if (lg > v1)       { vv2 = v1; j2 = j1; v1 = lg; j1 = e; }
            else if (lg > vv2) { vv2 = lg; j2 = e; }
        }
        const float w0s = 1.f / (1.f + __expf(vv2 - v1));   // softmax denom cancels
        const int i0s = j1, i1s = j2;

        // ---- combine (dim-sliced): warp covers dims [128w, 128w+128) ----
        #pragma unroll
        for (int t = 0; t < 8; t++) {
            const float w0 = __shfl_sync(FULL, w0s, t);
            const int   i0 = __shfl_sync(FULL, i0s, t);
            const int   i1 = __shfl_sync(FULL, i1s, t);
            const float w1 = 1.f - w0;
            float4 h4 = *(const float4*)&hbuf[t * DDIM + d0];
            float4 r0 = *(const float4*)(rt_e + i0 * DDIM + d0);
            float4 r1 = *(const float4*)(rt_e + i1 * DDIM + d0);
            float4 o;
            o.x = h4.x * (sh4.x + w0 * r0.x + w1 * r1.x);
            o.y = h4.y * (sh4.y + w0 * r0.y + w1 * r1.y);
            o.z = h4.z * (sh4.z + w0 * r0.z + w1 * r1.z);
            o.w = h4.w * (sh4.w + w0 * r0.w + w1 * r1.w);
            *(float4*)(out + (size_t)(tbase + t) * DDIM + d0) = o;
            s4x += h4.x * h4.x; s4y += h4.y * h4.y;
            s4z += h4.z * h4.z; s4w += h4.w * h4.w;
        }
        // no end-of-group barrier: next group's first barrier protects buffers
    }

    atomicAdd(&g_S[d0 + 0], s4x);
    atomicAdd(&g_S[d0 + 1], s4y);
    atomicAdd(&g_S[d0 + 2], s4z);
    atomicAdd(&g_S[d0 + 3], s4w);
}

// ============================================================================
// K2: d-parallel Gram. 64 blocks own 16-dim slices; thread = (e,f) pair;
//   smem-staged rt slice (pad 17) + S slice; one atomicAdd into g_G.
// ============================================================================
#define GBLK 64
#define GDIM (DDIM / GBLK)   // 16 dims per block

extern "C" __global__ void __launch_bounds__(256, 4)
moe_gram(const float* __restrict__ rt_e)
{
    __shared__ float rs[NEXP * 17];   // [e][j], padded
    __shared__ float Ss[GDIM];
    const int tid = threadIdx.x;
    const int dbase = blockIdx.x * GDIM;

    // stage: thread (e = tid>>4, j = tid&15)
    {
        const int e = tid >> 4, j = tid & 15;
        rs[e * 17 + j] = __ldg(&rt_e[e * DDIM + dbase + j]);
        if (tid < GDIM) Ss[tid] = g_S[dbase + tid];
    }
    __syncthreads();

    const int e = tid >> 4, f = tid & 15;
    float acc = 0.f;
    #pragma unroll
    for (int j = 0; j < GDIM; j++)
        acc += rs[e * 17 + j] * rs[f * 17 + j] * Ss[j];
    atomicAdd(&g_G[tid], acc);
}

// ============================================================================
// K3: final diversity loss; re-zero g_S and g_G for next graph replay
// ============================================================================
extern "C" __global__ void moe_loss(float* __restrict__ out, int has_loss, int loss_idx)
{
    const int lane = threadIdx.x;   // 32 threads
    const int e = lane & 15;
    float n = sqrtf(g_G[e * NEXP + e]);
    n = fmaxf(n, 1e-8f);
    float s = 0.f;
    #pragma unroll
    for (int f = 0; f < NEXP; f++) {
        float nf = __shfl_sync(FULL, n, f);
        if (f != e) {
            float sim = g_G[e * NEXP + f] / (n * nf);
            sim = fminf(1.f, fmaxf(-1.f, sim));
            s += sim;
        }
    }
    if (lane >= 16) s = 0.f;
    #pragma unroll
    for (int off = 16; off; off >>= 1) s += __shfl_xor_sync(FULL, s, off);
    if (lane == 0 && has_loss)
        out[loss_idx] = s / (float)(NEXP * (NEXP - 1)) * 0.1f;

    // restore invariants for the next iteration (graph replay safe)
    for (int i = lane; i < DDIM; i += 32) g_S[i] = 0.f;
    for (int i = lane; i < NEXP * NEXP; i += 32) g_G[i] = 0.f;
}

// ============================================================================
extern "C" void kernel_launch(void* const* d_in, const int* in_sizes, int n_in,
                              void* d_out, int out_size)
{
    const float* x  = (const float*)d_in[0];
    const float* gw = (const float*)d_in[1];
    const float* gb = (const float*)d_in[2];
    const float* se = (const float*)d_in[3];
    const float* re = (const float*)d_in[4];
    float* out = (float*)d_out;

    const int SMEM1 = 3 * HBUF * (int)sizeof(float);   // 96 KB dynamic
    cudaFuncSetAttribute((const void*)moe_main,
                         cudaFuncAttributeMaxDynamicSharedMemorySize, SMEM1);

    moe_main<<<NBLK, 256, SMEM1>>>(x, gw, gb, se, re, out);
    moe_gram<<<GBLK, 256>>>(re);

    int has_loss = (out_size > NTOK * DDIM) ? 1 : 0;
    moe_loss<<<1, 32>>>(out, has_loss, out_size - 1);
}